// round 11
// baseline (speedup 1.0000x reference)
#include <cuda_runtime.h>
#include <math.h>

// Problem constants
#define BB   2
#define TT   8192
#define HH   16
#define NBB  32
#define DD   1024
#define DHH  128
#define CHN  (HH*NBB)          // 512
#define MM   (BB*TT)           // 16384

// Scan chunking
#define SCAN_L 16
#define SCAN_C (TT/SCAN_L)     // 512 chunks
#define GRP    32              // chunks per group
#define NGRP   (SCAN_C/GRP)    // 16 groups

// Output layout: theta_hat [B,T,H,NB], d [B,T,H,NB], K_star [H,NB]
#define OFF_D  ((size_t)BB*TT*CHN)     // 8388608
#define OFF_K  (2*OFF_D)               // 16777216

// Scratch (static device allocations; no cudaMalloc allowed)
__device__ __align__(16) float g_hid [(size_t)MM*DHH];      // 8.4 MB
__device__ __align__(16) float g_part[(size_t)MM*DHH];      // 8.4 MB (split-K partial)
__device__ __align__(16) float g_nu  [(size_t)MM*CHN];      // 33.5 MB
__device__ __align__(16) float g_K[CHN];
__device__ __align__(16) float g_alpha[CHN];
__device__ __align__(16) float g_alphaL[CHN];               // alpha^SCAN_L
__device__ __align__(16) float g_alphaL32[CHN];             // alpha^(SCAN_L*GRP)
__device__ __align__(16) float g_aLp[GRP][CHN];             // alphaL^j
__device__ __align__(16) float g_Bmat[(size_t)BB*SCAN_C*CHN];  // 2 MB
__device__ __align__(16) float g_D0 [(size_t)BB*SCAN_C*CHN];   // 2 MB (within-group carries)
__device__ __align__(16) float g_G[(size_t)BB*NGRP*CHN];
__device__ __align__(16) float g_C[(size_t)BB*NGRP*CHN];

typedef unsigned long long ull;

// ---------------------------------------------------------------------------
// packed fp32x2 helpers (sm_103a FFMA2)
__device__ __forceinline__ void ffma2(ull& d, ull a, ull b) {
    asm("fma.rn.f32x2 %0, %1, %2, %0;" : "+l"(d) : "l"(a), "l"(b));
}
__device__ __forceinline__ ull pack2(float x) {
    ull r; asm("mov.b64 %0, {%1, %1};" : "=l"(r) : "f"(x)); return r;
}
__device__ __forceinline__ void unpack2(ull v, float& lo, float& hi) {
    asm("mov.b64 {%0, %1}, %2;" : "=f"(lo), "=f"(hi) : "l"(v));
}

// ---------------------------------------------------------------------------
// K* = (P+Q)/(P+Q+R),  P = (-Q + sqrt(Q^2+4QR))/2  + scan constants
__global__ void kstar_kernel(const float* __restrict__ lQ,
                             const float* __restrict__ lR,
                             float* __restrict__ out) {
    int c = threadIdx.x;  // 512
    float Q = expf(lQ[c]);
    float R = expf(lR[c]);
    float P_post = 0.5f * (-Q + sqrtf(Q * Q + 4.0f * Q * R));
    float P_pred = P_post + Q;
    float Kc = P_pred / (P_pred + R);
    float a = 1.0f - Kc;
    g_K[c] = Kc;
    g_alpha[c] = a;
    float aL = powf(a, (float)SCAN_L);
    g_alphaL[c] = aL;
    float p = 1.0f;
    #pragma unroll
    for (int j = 0; j < GRP; j++) { g_aLp[j][c] = p; p *= aL; }
    g_alphaL32[c] = p;                 // aL^GRP
    out[OFF_K + c] = Kc;
}

// ---------------------------------------------------------------------------
// FFMA2 tiled fp32 GEMM, double-buffered smem, packed-B (f32x2 pairs in smem).
// BM=BN=128, BK=16, 256 threads, 8x8 microtile, 2 CTAs/SM.
// EPI==0: raw partial -> (kz ? g_part : g_hid)  [GEMM1 split-K, grid (128, 2)]
// EPI==1: wrap(pi*tanh(. + b2) - theta) -> g_nu [GEMM2, grid (128, 4)]
#define BM 128
#define BN 128
#define BK 16

__device__ __forceinline__ float gelu_exact(float x) {
    return 0.5f * x * (1.0f + erff(x * 0.70710678118654752f));
}

template<int KDIM, int KSPLIT, int NSTRIDE, int EPI>
__global__ __launch_bounds__(256, 2)
void gemm_ffma2(const float* __restrict__ Ain,
                const float* __restrict__ Bw,
                const float* __restrict__ bias,
                const float* __restrict__ theta) {
    __shared__ __align__(16) float As[2][BK][BM];   // 16 KB
    __shared__ __align__(16) ull   Bsp[2][BK][BN];  // 32 KB (packed pairs)
    const int bm = blockIdx.x;
    const int bn = (KSPLIT > 1) ? 0 : blockIdx.y;
    const int kz = (KSPLIT > 1) ? blockIdx.y : 0;
    const int tid = threadIdx.x;
    const int ty = tid >> 4, tx = tid & 15;
    const int KSEG = KDIM / KSPLIT;

    const float* A = (EPI == 0) ? Ain : (const float*)g_hid;
    const float* Ablk = A + (size_t)bm * BM * KDIM + (size_t)kz * KSEG;
    const float* Bblk = Bw + (size_t)kz * KSEG * NSTRIDE + bn * BN;

    ull acc[4][8];
    #pragma unroll
    for (int p = 0; p < 4; p++)
        #pragma unroll
        for (int j = 0; j < 8; j++) acc[p][j] = 0ULL;

    float4 ra[2], rb[2];

    // A: 128 rows x 16 k = 512 float4 -> 2 per thread
    // B: 16 rows x 128 cols = 512 float4 -> 2 per thread
    #define LOADG(k0)                                                          \
        {                                                                      \
            _Pragma("unroll")                                                  \
            for (int it = 0; it < 2; it++) {                                   \
                int slot = it * 256 + tid;                                     \
                ra[it] = *(const float4*)(Ablk + (size_t)(slot >> 2) * KDIM +  \
                                          (k0) + (slot & 3) * 4);              \
                rb[it] = *(const float4*)(Bblk +                               \
                          (size_t)((k0) + (slot >> 5)) * NSTRIDE +             \
                          (slot & 31) * 4);                                    \
            }                                                                  \
        }
    #define STOS(buf)                                                          \
        {                                                                      \
            _Pragma("unroll")                                                  \
            for (int it = 0; it < 2; it++) {                                   \
                int slot = it * 256 + tid;                                     \
                int row = slot >> 2, k4 = (slot & 3) * 4;                      \
                As[buf][k4 + 0][row] = ra[it].x;                               \
                As[buf][k4 + 1][row] = ra[it].y;                               \
                As[buf][k4 + 2][row] = ra[it].z;                               \
                As[buf][k4 + 3][row] = ra[it].w;                               \
                int brow = slot >> 5, bcol = (slot & 31) * 4;                  \
                ulonglong2 p01 = {pack2(rb[it].x), pack2(rb[it].y)};           \
                ulonglong2 p23 = {pack2(rb[it].z), pack2(rb[it].w)};           \
                *(ulonglong2*)&Bsp[buf][brow][bcol]     = p01;                 \
                *(ulonglong2*)&Bsp[buf][brow][bcol + 2] = p23;                 \
            }                                                                  \
        }

    LOADG(0);
    STOS(0);
    __syncthreads();

    const int NT = KSEG / BK;
    int cur = 0;
    for (int t = 0; t < NT; t++) {
        if (t + 1 < NT) LOADG((t + 1) * BK);
        #pragma unroll
        for (int k = 0; k < BK; k++) {
            ulonglong2 a0 = *(const ulonglong2*)&As[cur][k][ty * 4];
            ulonglong2 a1 = *(const ulonglong2*)&As[cur][k][64 + ty * 4];
            ulonglong2 b01 = *(const ulonglong2*)&Bsp[cur][k][tx * 4];
            ulonglong2 b23 = *(const ulonglong2*)&Bsp[cur][k][tx * 4 + 2];
            ulonglong2 b45 = *(const ulonglong2*)&Bsp[cur][k][64 + tx * 4];
            ulonglong2 b67 = *(const ulonglong2*)&Bsp[cur][k][64 + tx * 4 + 2];
            ull ap[4] = {a0.x, a0.y, a1.x, a1.y};
            ull bb[8] = {b01.x, b01.y, b23.x, b23.y,
                         b45.x, b45.y, b67.x, b67.y};
            #pragma unroll
            for (int p = 0; p < 4; p++)
                #pragma unroll
                for (int j = 0; j < 8; j++)
                    ffma2(acc[p][j], ap[p], bb[j]);
        }
        if (t + 1 < NT) STOS(cur ^ 1);
        __syncthreads();
        cur ^= 1;
    }

    // --- epilogue ---
    const float PI_F     = 3.14159265358979323846f;
    const float INV_2PI  = 0.15915494309189533577f;
    const float TWO_PI   = 6.28318530717958647693f;
    float* Cp = kz ? (float*)g_part : (float*)g_hid;
    #pragma unroll
    for (int p = 0; p < 4; p++) {
        int rl = (p >> 1) * 64 + ty * 4 + (p & 1) * 2;
        #pragma unroll
        for (int lane = 0; lane < 2; lane++) {
            int row = bm * BM + rl + lane;
            float v[8];
            #pragma unroll
            for (int j = 0; j < 8; j++) {
                float lo, hi;
                unpack2(acc[p][j], lo, hi);
                v[j] = lane ? hi : lo;
            }
            #pragma unroll
            for (int half = 0; half < 2; half++) {
                int coll = half * 64 + tx * 4;
                if (EPI == 0) {
                    float4 o = {v[half*4+0], v[half*4+1], v[half*4+2], v[half*4+3]};
                    *(float4*)&Cp[(size_t)row * DHH + coll] = o;
                } else {
                    int col = bn * BN + coll;
                    float4 th = *(const float4*)&theta[(size_t)row * CHN + col];
                    const float* pth = (const float*)&th;
                    float4 o;
                    float* po = (float*)&o;
                    #pragma unroll
                    for (int j = 0; j < 4; j++) {
                        float zr = v[half * 4 + j] + bias[col + j];
                        float z = PI_F * tanhf(zr);
                        float dif = z - pth[j];
                        po[j] = dif - TWO_PI * rintf(dif * INV_2PI);
                    }
                    *(float4*)&g_nu[(size_t)row * CHN + col] = o;
                }
            }
        }
    }
    #undef LOADG
    #undef STOS
}

// ---------------------------------------------------------------------------
// combine split-K partials: g_hid = gelu(g_hid + g_part + b1)
__global__ __launch_bounds__(256)
void combine_gelu(const float* __restrict__ bias) {
    const size_t n4 = (size_t)MM * DHH / 4;
    size_t i = (size_t)blockIdx.x * blockDim.x + threadIdx.x;
    const size_t stride = (size_t)gridDim.x * blockDim.x;
    for (; i < n4; i += stride) {
        float4 h = ((const float4*)g_hid)[i];
        float4 p = ((const float4*)g_part)[i];
        int colb = ((int)(i & 31)) * 4;      // DHH=128 -> 32 float4 per row
        float4 o;
        o.x = gelu_exact(h.x + p.x + bias[colb + 0]);
        o.y = gelu_exact(h.y + p.y + bias[colb + 1]);
        o.z = gelu_exact(h.z + p.z + bias[colb + 2]);
        o.w = gelu_exact(h.w + p.w + bias[colb + 3]);
        ((float4*)g_hid)[i] = o;
    }
}

// ---------------------------------------------------------------------------
// Scan pass 1: per-(b,chunk,ch4) B_c = sum_{i<L} alpha^(L-1-i) K nu_i.
// Each block handles 2 chunks (2 independent chains -> 2x MLP).
__global__ void scan_pass1() {
    int t = threadIdx.x;        // 128 threads, 4 channels each
    int c0 = blockIdx.x * 2;
    int b  = blockIdx.y;
    const float4 a4 = ((const float4*)g_alpha)[t];
    const float4 K4 = ((const float4*)g_K)[t];
    const float4* nu0 = (const float4*)g_nu +
                        ((size_t)b * TT + (size_t)c0 * SCAN_L) * (CHN / 4) + t;
    const float4* nu1 = nu0 + (size_t)SCAN_L * (CHN / 4);
    float4 s0 = {0.f,0.f,0.f,0.f}, s1 = {0.f,0.f,0.f,0.f};
    #pragma unroll
    for (int i = 0; i < SCAN_L; i++) {
        float4 v0 = nu0[(size_t)i * (CHN / 4)];
        float4 v1 = nu1[(size_t)i * (CHN / 4)];
        s0.x = fmaf(a4.x, s0.x, K4.x * v0.x);
        s0.y = fmaf(a4.y, s0.y, K4.y * v0.y);
        s0.z = fmaf(a4.z, s0.z, K4.z * v0.z);
        s0.w = fmaf(a4.w, s0.w, K4.w * v0.w);
        s1.x = fmaf(a4.x, s1.x, K4.x * v1.x);
        s1.y = fmaf(a4.y, s1.y, K4.y * v1.y);
        s1.z = fmaf(a4.z, s1.z, K4.z * v1.z);
        s1.w = fmaf(a4.w, s1.w, K4.w * v1.w);
    }
    ((float4*)g_Bmat)[((size_t)b * SCAN_C + c0) * (CHN / 4) + t] = s0;
    ((float4*)g_Bmat)[((size_t)b * SCAN_C + c0 + 1) * (CHN / 4) + t] = s1;
}

// Scan pass 2a: within-group carries (grid NGRP x BB). D0[c]=carry before chunk c
// (group-local), G[g]=full-group aggregate.
__global__ void scan_pass2a() {
    int t = threadIdx.x;        // 128
    int g = blockIdx.x;         // 16
    int b = blockIdx.y;
    const float4 aL = ((const float4*)g_alphaL)[t];
    float4 carry = {0.f, 0.f, 0.f, 0.f};
    #pragma unroll 4
    for (int j = 0; j < GRP; j++) {
        size_t idx = ((size_t)b * SCAN_C + g * GRP + j) * (CHN / 4) + t;
        ((float4*)g_D0)[idx] = carry;
        float4 Bv = ((const float4*)g_Bmat)[idx];
        carry.x = fmaf(aL.x, carry.x, Bv.x);
        carry.y = fmaf(aL.y, carry.y, Bv.y);
        carry.z = fmaf(aL.z, carry.z, Bv.z);
        carry.w = fmaf(aL.w, carry.w, Bv.w);
    }
    ((float4*)g_G)[((size_t)b * NGRP + g) * (CHN / 4) + t] = carry;
}

// Scan pass 2b: scan group aggregates (16 serial steps). C[g]=carry entering group g.
__global__ void scan_pass2b() {
    int t = threadIdx.x;        // 128
    int b = blockIdx.x;         // 2
    const float4 aL32 = ((const float4*)g_alphaL32)[t];
    float4 carry = {0.f, 0.f, 0.f, 0.f};
    #pragma unroll
    for (int g = 0; g < NGRP; g++) {
        size_t idx = ((size_t)b * NGRP + g) * (CHN / 4) + t;
        ((float4*)g_C)[idx] = carry;
        float4 Gv = ((const float4*)g_G)[idx];
        carry.x = fmaf(aL32.x, carry.x, Gv.x);
        carry.y = fmaf(aL32.y, carry.y, Gv.y);
        carry.z = fmaf(aL32.z, carry.z, Gv.z);
        carry.w = fmaf(aL32.w, carry.w, Gv.w);
    }
}

// Scan pass 3: replay 2 chunks per block with full carry, write d and theta_hat.
__global__ void scan_pass3(const float* __restrict__ theta,
                           float* __restrict__ out) {
    int t = threadIdx.x;
    int c0 = blockIdx.x * 2;
    int b  = blockIdx.y;
    const float4 a4 = ((const float4*)g_alpha)[t];
    const float4 K4 = ((const float4*)g_K)[t];

    float4 d[2];
    #pragma unroll
    for (int cc = 0; cc < 2; cc++) {
        int c = c0 + cc;
        int g = c >> 5, jl = c & 31;
        float4 d0 = ((const float4*)g_D0)[((size_t)b * SCAN_C + c) * (CHN / 4) + t];
        float4 Cg = ((const float4*)g_C)[((size_t)b * NGRP + g) * (CHN / 4) + t];
        float4 ap = ((const float4*)g_aLp)[(size_t)jl * (CHN / 4) + t];
        d[cc].x = fmaf(Cg.x, ap.x, d0.x);
        d[cc].y = fmaf(Cg.y, ap.y, d0.y);
        d[cc].z = fmaf(Cg.z, ap.z, d0.z);
        d[cc].w = fmaf(Cg.w, ap.w, d0.w);
    }

    size_t base = ((size_t)b * TT + (size_t)c0 * SCAN_L) * (CHN / 4) + t;
    const float4* nu4 = (const float4*)g_nu + base;
    const float4* th4 = (const float4*)theta + base;
    float4* outh = (float4*)out + base;
    float4* outd = (float4*)(out + OFF_D) + base;
    const size_t cstep = (size_t)SCAN_L * (CHN / 4);
    #pragma unroll
    for (int i = 0; i < SCAN_L; i++) {
        size_t i0 = (size_t)i * (CHN / 4);
        size_t i1 = i0 + cstep;
        float4 v0 = nu4[i0], v1 = nu4[i1];
        float4 t0 = th4[i0], t1 = th4[i1];
        d[0].x = fmaf(a4.x, d[0].x, K4.x * v0.x);
        d[0].y = fmaf(a4.y, d[0].y, K4.y * v0.y);
        d[0].z = fmaf(a4.z, d[0].z, K4.z * v0.z);
        d[0].w = fmaf(a4.w, d[0].w, K4.w * v0.w);
        d[1].x = fmaf(a4.x, d[1].x, K4.x * v1.x);
        d[1].y = fmaf(a4.y, d[1].y, K4.y * v1.y);
        d[1].z = fmaf(a4.z, d[1].z, K4.z * v1.z);
        d[1].w = fmaf(a4.w, d[1].w, K4.w * v1.w);
        outd[i0] = d[0];
        outd[i1] = d[1];
        float4 o0 = {t0.x + d[0].x, t0.y + d[0].y, t0.z + d[0].z, t0.w + d[0].w};
        float4 o1 = {t1.x + d[1].x, t1.y + d[1].y, t1.z + d[1].z, t1.w + d[1].w};
        outh[i0] = o0;
        outh[i1] = o1;
    }
}

// ---------------------------------------------------------------------------
extern "C" void kernel_launch(void* const* d_in, const int* in_sizes, int n_in,
                              void* d_out, int out_size) {
    const float* theta   = (const float*)d_in[0];  // (B,T,H,NB)
    const float* content = (const float*)d_in[1];  // (B,T,D)
    const float* W1      = (const float*)d_in[2];  // (D,DH)
    const float* b1      = (const float*)d_in[3];  // (DH,)
    const float* W2      = (const float*)d_in[4];  // (DH,H*NB)
    const float* b2      = (const float*)d_in[5];  // (H*NB,)
    const float* lQ      = (const float*)d_in[6];  // (H,NB)
    const float* lR      = (const float*)d_in[7];  // (H,NB)
    float* out = (float*)d_out;

    kstar_kernel<<<1, CHN>>>(lQ, lR, out);
    // GEMM1 split-K=2: raw partials into g_hid / g_part
    gemm_ffma2<DD, 2, DHH, 0><<<dim3(MM / BM, 2), 256>>>(content, W1, b1, nullptr);
    combine_gelu<<<2048, 256>>>(b1);
    // GEMM2
    gemm_ffma2<DHH, 1, CHN, 1><<<dim3(MM / BM, CHN / BN), 256>>>(nullptr, W2, b2, theta);
    scan_pass1<<<dim3(SCAN_C / 2, BB), 128>>>();
    scan_pass2a<<<dim3(NGRP, BB), 128>>>();
    scan_pass2b<<<BB, 128>>>();
    scan_pass3<<<dim3(SCAN_C / 2, BB), 128>>>(theta, out);
}

// round 12
// speedup vs baseline: 1.1815x; 1.1815x over previous
#include <cuda_runtime.h>
#include <math.h>

// Problem constants
#define BB   2
#define TT   8192
#define HH   16
#define NBB  32
#define DD   1024
#define DHH  128
#define CHN  (HH*NBB)          // 512
#define MM   (BB*TT)           // 16384

// Scan chunking
#define SCAN_L 16
#define SCAN_C (TT/SCAN_L)     // 512 chunks
#define GRP    32              // chunks per group
#define NGRP   (SCAN_C/GRP)    // 16 groups

// Output layout: theta_hat [B,T,H,NB], d [B,T,H,NB], K_star [H,NB]
#define OFF_D  ((size_t)BB*TT*CHN)     // 8388608
#define OFF_K  (2*OFF_D)               // 16777216

// Scratch (static device allocations; no cudaMalloc allowed)
__device__ __align__(16) float g_hid [(size_t)MM*DHH];      // 8.4 MB
__device__ __align__(16) float g_part[(size_t)MM*DHH];      // 8.4 MB (split-K partial)
__device__ __align__(16) float g_nu  [(size_t)MM*CHN];      // 33.5 MB
__device__ __align__(16) float g_K[CHN];
__device__ __align__(16) float g_alpha[CHN];
__device__ __align__(16) float g_alphaL[CHN];               // alpha^SCAN_L
__device__ __align__(16) float g_alphaL32[CHN];             // alpha^(SCAN_L*GRP)
__device__ __align__(16) float g_aLp[GRP][CHN];             // alphaL^j
__device__ __align__(16) float g_Bmat[(size_t)BB*SCAN_C*CHN];  // 2 MB
__device__ __align__(16) float g_D0 [(size_t)BB*SCAN_C*CHN];   // 2 MB
__device__ __align__(16) float g_G[(size_t)BB*NGRP*CHN];
__device__ __align__(16) float g_C[(size_t)BB*NGRP*CHN];

typedef unsigned long long ull;

// ---------------------------------------------------------------------------
// packed fp32x2 helpers (sm_103a FFMA2)
__device__ __forceinline__ void ffma2(ull& d, ull a, ull b) {
    asm("fma.rn.f32x2 %0, %1, %2, %0;" : "+l"(d) : "l"(a), "l"(b));
}
__device__ __forceinline__ ull pack2(float x) {
    ull r; asm("mov.b64 %0, {%1, %1};" : "=l"(r) : "f"(x)); return r;
}
__device__ __forceinline__ void unpack2(ull v, float& lo, float& hi) {
    asm("mov.b64 {%0, %1}, %2;" : "=f"(lo), "=f"(hi) : "l"(v));
}

// ---------------------------------------------------------------------------
// K* = (P+Q)/(P+Q+R),  P = (-Q + sqrt(Q^2+4QR))/2  + scan constants
__global__ void kstar_kernel(const float* __restrict__ lQ,
                             const float* __restrict__ lR,
                             float* __restrict__ out) {
    int c = threadIdx.x;  // 512
    float Q = expf(lQ[c]);
    float R = expf(lR[c]);
    float P_post = 0.5f * (-Q + sqrtf(Q * Q + 4.0f * Q * R));
    float P_pred = P_post + Q;
    float Kc = P_pred / (P_pred + R);
    float a = 1.0f - Kc;
    g_K[c] = Kc;
    g_alpha[c] = a;
    float aL = powf(a, (float)SCAN_L);
    g_alphaL[c] = aL;
    float p = 1.0f;
    #pragma unroll
    for (int j = 0; j < GRP; j++) { g_aLp[j][c] = p; p *= aL; }
    g_alphaL32[c] = p;                 // aL^GRP
    out[OFF_K + c] = Kc;
}

// ---------------------------------------------------------------------------
// FFMA2 tiled fp32 GEMM, double-buffered smem.
// Microtile pairs run along N: acc[m][np] holds (n, n+1) packed pairs.
//   - B stays plain float32 in smem; ulonglong2 reads give natural (b,b+1) pairs.
//   - A is stored PACKED (a,a) in smem at store time -> zero inner-loop MOVs.
// BM=BN=128, BK=16, 256 threads, 8(M) x 8(N) microtile, 2 CTAs/SM.
// EPI==0: raw partial -> (kz ? g_part : g_hid)  [GEMM1 split-K, grid (128, 2)]
// EPI==1: wrap(pi*tanh(. + b2) - theta) -> g_nu [GEMM2, grid (128, 4)]
#define BM 128
#define BN 128
#define BK 16

__device__ __forceinline__ float gelu_exact(float x) {
    return 0.5f * x * (1.0f + erff(x * 0.70710678118654752f));
}

template<int KDIM, int KSPLIT, int NSTRIDE, int EPI>
__global__ __launch_bounds__(256, 2)
void gemm_ffma2(const float* __restrict__ Ain,
                const float* __restrict__ Bw,
                const float* __restrict__ bias,
                const float* __restrict__ theta) {
    __shared__ __align__(16) ull   Asp[2][BK][BM];  // 32 KB (packed (a,a))
    __shared__ __align__(16) float Bs [2][BK][BN];  // 16 KB (plain f32)
    const int bm = blockIdx.x;
    const int bn = (KSPLIT > 1) ? 0 : blockIdx.y;
    const int kz = (KSPLIT > 1) ? blockIdx.y : 0;
    const int tid = threadIdx.x;
    const int ty = tid >> 4, tx = tid & 15;   // both 0..15
    const int KSEG = KDIM / KSPLIT;

    const float* A = (EPI == 0) ? Ain : (const float*)g_hid;
    const float* Ablk = A + (size_t)bm * BM * KDIM + (size_t)kz * KSEG;
    const float* Bblk = Bw + (size_t)kz * KSEG * NSTRIDE + bn * BN;

    // acc[m][np]: m = M-row (ty*8+m), np = packed N pair (cols tx*8+2np, +2np+1)
    ull acc[8][4];
    #pragma unroll
    for (int m = 0; m < 8; m++)
        #pragma unroll
        for (int n = 0; n < 4; n++) acc[m][n] = 0ULL;

    float4 ra[2], rb[2];

    // A: 128 rows x 16 k = 512 float4 -> 2 per thread
    // B: 16 rows x 128 cols = 512 float4 -> 2 per thread
    #define LOADG(k0)                                                          \
        {                                                                      \
            _Pragma("unroll")                                                  \
            for (int it = 0; it < 2; it++) {                                   \
                int slot = it * 256 + tid;                                     \
                ra[it] = *(const float4*)(Ablk + (size_t)(slot >> 2) * KDIM +  \
                                          (k0) + (slot & 3) * 4);              \
                rb[it] = *(const float4*)(Bblk +                               \
                          (size_t)((k0) + (slot >> 5)) * NSTRIDE +             \
                          (slot & 31) * 4);                                    \
            }                                                                  \
        }
    #define STOS(buf)                                                          \
        {                                                                      \
            _Pragma("unroll")                                                  \
            for (int it = 0; it < 2; it++) {                                   \
                int slot = it * 256 + tid;                                     \
                int row = slot >> 2, k4 = (slot & 3) * 4;                      \
                Asp[buf][k4 + 0][row] = pack2(ra[it].x);                       \
                Asp[buf][k4 + 1][row] = pack2(ra[it].y);                       \
                Asp[buf][k4 + 2][row] = pack2(ra[it].z);                       \
                Asp[buf][k4 + 3][row] = pack2(ra[it].w);                       \
                *(float4*)&Bs[buf][slot >> 5][(slot & 31) * 4] = rb[it];       \
            }                                                                  \
        }

    LOADG(0);
    STOS(0);
    __syncthreads();

    const int NT = KSEG / BK;
    int cur = 0;
    for (int t = 0; t < NT; t++) {
        if (t + 1 < NT) LOADG((t + 1) * BK);
        #pragma unroll
        for (int k = 0; k < BK; k++) {
            ulonglong2 a01 = *(const ulonglong2*)&Asp[cur][k][ty * 8];
            ulonglong2 a23 = *(const ulonglong2*)&Asp[cur][k][ty * 8 + 2];
            ulonglong2 a45 = *(const ulonglong2*)&Asp[cur][k][ty * 8 + 4];
            ulonglong2 a67 = *(const ulonglong2*)&Asp[cur][k][ty * 8 + 6];
            ulonglong2 b03 = *(const ulonglong2*)&Bs[cur][k][tx * 8];
            ulonglong2 b47 = *(const ulonglong2*)&Bs[cur][k][tx * 8 + 4];
            ull ap[8] = {a01.x, a01.y, a23.x, a23.y,
                         a45.x, a45.y, a67.x, a67.y};
            ull bp[4] = {b03.x, b03.y, b47.x, b47.y};
            #pragma unroll
            for (int m = 0; m < 8; m++)
                #pragma unroll
                for (int n = 0; n < 4; n++)
                    ffma2(acc[m][n], ap[m], bp[n]);
        }
        if (t + 1 < NT) STOS(cur ^ 1);
        __syncthreads();
        cur ^= 1;
    }

    // --- epilogue ---
    // Thread owns rows bm*128 + ty*8 + m (m=0..7), cols bn*128 + tx*8 + 0..7.
    const float PI_F     = 3.14159265358979323846f;
    const float INV_2PI  = 0.15915494309189533577f;
    const float TWO_PI   = 6.28318530717958647693f;
    float* Cp = kz ? (float*)g_part : (float*)g_hid;
    #pragma unroll
    for (int m = 0; m < 8; m++) {
        int row = bm * BM + ty * 8 + m;
        float v[8];
        #pragma unroll
        for (int n = 0; n < 4; n++) unpack2(acc[m][n], v[2 * n], v[2 * n + 1]);
        #pragma unroll
        for (int half = 0; half < 2; half++) {
            int coll = tx * 8 + half * 4;
            if (EPI == 0) {
                float4 o = {v[half*4+0], v[half*4+1], v[half*4+2], v[half*4+3]};
                *(float4*)&Cp[(size_t)row * DHH + coll] = o;
            } else {
                int col = bn * BN + coll;
                float4 th = *(const float4*)&theta[(size_t)row * CHN + col];
                const float* pth = (const float*)&th;
                float4 o;
                float* po = (float*)&o;
                #pragma unroll
                for (int j = 0; j < 4; j++) {
                    float zr = v[half * 4 + j] + bias[col + j];
                    float z = PI_F * tanhf(zr);
                    float dif = z - pth[j];
                    po[j] = dif - TWO_PI * rintf(dif * INV_2PI);
                }
                *(float4*)&g_nu[(size_t)row * CHN + col] = o;
            }
        }
    }
    #undef LOADG
    #undef STOS
}

// ---------------------------------------------------------------------------
// combine split-K partials: g_hid = gelu(g_hid + g_part + b1)
__global__ __launch_bounds__(256)
void combine_gelu(const float* __restrict__ bias) {
    const size_t n4 = (size_t)MM * DHH / 4;
    size_t i = (size_t)blockIdx.x * blockDim.x + threadIdx.x;
    const size_t stride = (size_t)gridDim.x * blockDim.x;
    for (; i < n4; i += stride) {
        float4 h = ((const float4*)g_hid)[i];
        float4 p = ((const float4*)g_part)[i];
        int colb = ((int)(i & 31)) * 4;      // DHH=128 -> 32 float4 per row
        float4 o;
        o.x = gelu_exact(h.x + p.x + bias[colb + 0]);
        o.y = gelu_exact(h.y + p.y + bias[colb + 1]);
        o.z = gelu_exact(h.z + p.z + bias[colb + 2]);
        o.w = gelu_exact(h.w + p.w + bias[colb + 3]);
        ((float4*)g_hid)[i] = o;
    }
}

// ---------------------------------------------------------------------------
// Scan pass 1: per-(b,chunk,ch4) B_c = sum_{i<L} alpha^(L-1-i) K nu_i.
// Each block handles 2 chunks (2 independent chains -> 2x MLP).
__global__ void scan_pass1() {
    int t = threadIdx.x;        // 128 threads, 4 channels each
    int c0 = blockIdx.x * 2;
    int b  = blockIdx.y;
    const float4 a4 = ((const float4*)g_alpha)[t];
    const float4 K4 = ((const float4*)g_K)[t];
    const float4* nu0 = (const float4*)g_nu +
                        ((size_t)b * TT + (size_t)c0 * SCAN_L) * (CHN / 4) + t;
    const float4* nu1 = nu0 + (size_t)SCAN_L * (CHN / 4);
    float4 s0 = {0.f,0.f,0.f,0.f}, s1 = {0.f,0.f,0.f,0.f};
    #pragma unroll
    for (int i = 0; i < SCAN_L; i++) {
        float4 v0 = nu0[(size_t)i * (CHN / 4)];
        float4 v1 = nu1[(size_t)i * (CHN / 4)];
        s0.x = fmaf(a4.x, s0.x, K4.x * v0.x);
        s0.y = fmaf(a4.y, s0.y, K4.y * v0.y);
        s0.z = fmaf(a4.z, s0.z, K4.z * v0.z);
        s0.w = fmaf(a4.w, s0.w, K4.w * v0.w);
        s1.x = fmaf(a4.x, s1.x, K4.x * v1.x);
        s1.y = fmaf(a4.y, s1.y, K4.y * v1.y);
        s1.z = fmaf(a4.z, s1.z, K4.z * v1.z);
        s1.w = fmaf(a4.w, s1.w, K4.w * v1.w);
    }
    ((float4*)g_Bmat)[((size_t)b * SCAN_C + c0) * (CHN / 4) + t] = s0;
    ((float4*)g_Bmat)[((size_t)b * SCAN_C + c0 + 1) * (CHN / 4) + t] = s1;
}

// Scan pass 2a: within-group carries (grid NGRP x BB).
__global__ void scan_pass2a() {
    int t = threadIdx.x;        // 128
    int g = blockIdx.x;         // 16
    int b = blockIdx.y;
    const float4 aL = ((const float4*)g_alphaL)[t];
    float4 carry = {0.f, 0.f, 0.f, 0.f};
    #pragma unroll 4
    for (int j = 0; j < GRP; j++) {
        size_t idx = ((size_t)b * SCAN_C + g * GRP + j) * (CHN / 4) + t;
        ((float4*)g_D0)[idx] = carry;
        float4 Bv = ((const float4*)g_Bmat)[idx];
        carry.x = fmaf(aL.x, carry.x, Bv.x);
        carry.y = fmaf(aL.y, carry.y, Bv.y);
        carry.z = fmaf(aL.z, carry.z, Bv.z);
        carry.w = fmaf(aL.w, carry.w, Bv.w);
    }
    ((float4*)g_G)[((size_t)b * NGRP + g) * (CHN / 4) + t] = carry;
}

// Scan pass 2b: scan group aggregates (16 serial steps).
__global__ void scan_pass2b() {
    int t = threadIdx.x;        // 128
    int b = blockIdx.x;         // 2
    const float4 aL32 = ((const float4*)g_alphaL32)[t];
    float4 carry = {0.f, 0.f, 0.f, 0.f};
    #pragma unroll
    for (int g = 0; g < NGRP; g++) {
        size_t idx = ((size_t)b * NGRP + g) * (CHN / 4) + t;
        ((float4*)g_C)[idx] = carry;
        float4 Gv = ((const float4*)g_G)[idx];
        carry.x = fmaf(aL32.x, carry.x, Gv.x);
        carry.y = fmaf(aL32.y, carry.y, Gv.y);
        carry.z = fmaf(aL32.z, carry.z, Gv.z);
        carry.w = fmaf(aL32.w, carry.w, Gv.w);
    }
}

// Scan pass 3: replay 2 chunks per block with full carry, write d and theta_hat.
__global__ void scan_pass3(const float* __restrict__ theta,
                           float* __restrict__ out) {
    int t = threadIdx.x;
    int c0 = blockIdx.x * 2;
    int b  = blockIdx.y;
    const float4 a4 = ((const float4*)g_alpha)[t];
    const float4 K4 = ((const float4*)g_K)[t];

    float4 d[2];
    #pragma unroll
    for (int cc = 0; cc < 2; cc++) {
        int c = c0 + cc;
        int g = c >> 5, jl = c & 31;
        float4 d0 = ((const float4*)g_D0)[((size_t)b * SCAN_C + c) * (CHN / 4) + t];
        float4 Cg = ((const float4*)g_C)[((size_t)b * NGRP + g) * (CHN / 4) + t];
        float4 ap = ((const float4*)g_aLp)[(size_t)jl * (CHN / 4) + t];
        d[cc].x = fmaf(Cg.x, ap.x, d0.x);
        d[cc].y = fmaf(Cg.y, ap.y, d0.y);
        d[cc].z = fmaf(Cg.z, ap.z, d0.z);
        d[cc].w = fmaf(Cg.w, ap.w, d0.w);
    }

    size_t base = ((size_t)b * TT + (size_t)c0 * SCAN_L) * (CHN / 4) + t;
    const float4* nu4 = (const float4*)g_nu + base;
    const float4* th4 = (const float4*)theta + base;
    float4* outh = (float4*)out + base;
    float4* outd = (float4*)(out + OFF_D) + base;
    const size_t cstep = (size_t)SCAN_L * (CHN / 4);
    #pragma unroll
    for (int i = 0; i < SCAN_L; i++) {
        size_t i0 = (size_t)i * (CHN / 4);
        size_t i1 = i0 + cstep;
        float4 v0 = nu4[i0], v1 = nu4[i1];
        float4 t0 = th4[i0], t1 = th4[i1];
        d[0].x = fmaf(a4.x, d[0].x, K4.x * v0.x);
        d[0].y = fmaf(a4.y, d[0].y, K4.y * v0.y);
        d[0].z = fmaf(a4.z, d[0].z, K4.z * v0.z);
        d[0].w = fmaf(a4.w, d[0].w, K4.w * v0.w);
        d[1].x = fmaf(a4.x, d[1].x, K4.x * v1.x);
        d[1].y = fmaf(a4.y, d[1].y, K4.y * v1.y);
        d[1].z = fmaf(a4.z, d[1].z, K4.z * v1.z);
        d[1].w = fmaf(a4.w, d[1].w, K4.w * v1.w);
        outd[i0] = d[0];
        outd[i1] = d[1];
        float4 o0 = {t0.x + d[0].x, t0.y + d[0].y, t0.z + d[0].z, t0.w + d[0].w};
        float4 o1 = {t1.x + d[1].x, t1.y + d[1].y, t1.z + d[1].z, t1.w + d[1].w};
        outh[i0] = o0;
        outh[i1] = o1;
    }
}

// ---------------------------------------------------------------------------
extern "C" void kernel_launch(void* const* d_in, const int* in_sizes, int n_in,
                              void* d_out, int out_size) {
    const float* theta   = (const float*)d_in[0];  // (B,T,H,NB)
    const float* content = (const float*)d_in[1];  // (B,T,D)
    const float* W1      = (const float*)d_in[2];  // (D,DH)
    const float* b1      = (const float*)d_in[3];  // (DH,)
    const float* W2      = (const float*)d_in[4];  // (DH,H*NB)
    const float* b2      = (const float*)d_in[5];  // (H*NB,)
    const float* lQ      = (const float*)d_in[6];  // (H,NB)
    const float* lR      = (const float*)d_in[7];  // (H,NB)
    float* out = (float*)d_out;

    kstar_kernel<<<1, CHN>>>(lQ, lR, out);
    // GEMM1 split-K=2: raw partials into g_hid / g_part
    gemm_ffma2<DD, 2, DHH, 0><<<dim3(MM / BM, 2), 256>>>(content, W1, b1, nullptr);
    combine_gelu<<<2048, 256>>>(b1);
    // GEMM2
    gemm_ffma2<DHH, 1, CHN, 1><<<dim3(MM / BM, CHN / BN), 256>>>(nullptr, W2, b2, theta);
    scan_pass1<<<dim3(SCAN_C / 2, BB), 128>>>();
    scan_pass2a<<<dim3(NGRP, BB), 128>>>();
    scan_pass2b<<<BB, 128>>>();
    scan_pass3<<<dim3(SCAN_C / 2, BB), 128>>>(theta, out);
}

// round 13
// speedup vs baseline: 1.4430x; 1.2214x over previous
#include <cuda_runtime.h>
#include <math.h>

// Problem constants
#define BB   2
#define TT   8192
#define HH   16
#define NBB  32
#define DD   1024
#define DHH  128
#define CHN  (HH*NBB)          // 512
#define MM   (BB*TT)           // 16384

// Scan chunking
#define SCAN_L 16
#define SCAN_C (TT/SCAN_L)     // 512 chunks
#define GRP    32              // chunks per group
#define NGRP   (SCAN_C/GRP)    // 16 groups

// Output layout: theta_hat [B,T,H,NB], d [B,T,H,NB], K_star [H,NB]
#define OFF_D  ((size_t)BB*TT*CHN)     // 8388608
#define OFF_K  (2*OFF_D)               // 16777216

// Scratch (static device allocations; no cudaMalloc allowed)
__device__ __align__(16) float g_hid [(size_t)MM*DHH];      // 8.4 MB
__device__ __align__(16) float g_part[(size_t)MM*DHH];      // 8.4 MB (split-K partial)
__device__ __align__(16) float g_nu  [(size_t)MM*CHN];      // 33.5 MB
__device__ __align__(16) float g_K[CHN];
__device__ __align__(16) float g_alpha[CHN];
__device__ __align__(16) float g_alphaL[CHN];               // alpha^SCAN_L
__device__ __align__(16) float g_alphaL32[CHN];             // alpha^(SCAN_L*GRP)
__device__ __align__(16) float g_aLp[GRP][CHN];             // alphaL^j
__device__ __align__(16) float g_Bmat[(size_t)BB*SCAN_C*CHN];  // 2 MB
__device__ __align__(16) float g_D0 [(size_t)BB*SCAN_C*CHN];   // 2 MB
__device__ __align__(16) float g_G[(size_t)BB*NGRP*CHN];
__device__ __align__(16) float g_C[(size_t)BB*NGRP*CHN];

typedef unsigned long long ull;

// ---------------------------------------------------------------------------
// packed fp32x2 helpers (sm_103a FFMA2)
__device__ __forceinline__ void ffma2(ull& d, ull a, ull b) {
    asm("fma.rn.f32x2 %0, %1, %2, %0;" : "+l"(d) : "l"(a), "l"(b));
}
__device__ __forceinline__ ull pack2(float x) {
    ull r; asm("mov.b64 %0, {%1, %1};" : "=l"(r) : "f"(x)); return r;
}
__device__ __forceinline__ void unpack2(ull v, float& lo, float& hi) {
    asm("mov.b64 {%0, %1}, %2;" : "=f"(lo), "=f"(hi) : "l"(v));
}

// ---------------------------------------------------------------------------
// K* = (P+Q)/(P+Q+R),  P = (-Q + sqrt(Q^2+4QR))/2  + scan constants
__global__ void kstar_kernel(const float* __restrict__ lQ,
                             const float* __restrict__ lR,
                             float* __restrict__ out) {
    int c = threadIdx.x;  // 512
    float Q = expf(lQ[c]);
    float R = expf(lR[c]);
    float P_post = 0.5f * (-Q + sqrtf(Q * Q + 4.0f * Q * R));
    float P_pred = P_post + Q;
    float Kc = P_pred / (P_pred + R);
    float a = 1.0f - Kc;
    g_K[c] = Kc;
    g_alpha[c] = a;
    float aL = powf(a, (float)SCAN_L);
    g_alphaL[c] = aL;
    float p = 1.0f;
    #pragma unroll
    for (int j = 0; j < GRP; j++) { g_aLp[j][c] = p; p *= aL; }
    g_alphaL32[c] = p;                 // aL^GRP
    out[OFF_K + c] = Kc;
}

// ---------------------------------------------------------------------------
// FFMA2 tiled fp32 GEMM, double-buffered smem, 2D warp tiling.
// CTA tile 128x128, BK=16, 256 threads.
// Warp grid 4(M) x 2(N): warp tile 32M x 64N. Lanes 4(lm) x 8(ln): thread 8Mx8N.
// Accumulators packed along N: acc[m][np] = (n, n+1) f32x2 pairs.
// B plain f32 smem, natural ulonglong2 pair reads (1 wavefront each).
// A plain f32 smem, 2 LDS.128 + 8 register pack2 MOVs per k.
// EPI==0: raw partial -> (kz ? g_part : g_hid)  [GEMM1 split-K, grid (128, 2)]
// EPI==1: wrap(pi*tanh(. + b2) - theta) -> g_nu [GEMM2, grid (128, 4)]
#define BM 128
#define BN 128
#define BK 16

__device__ __forceinline__ float gelu_exact(float x) {
    return 0.5f * x * (1.0f + erff(x * 0.70710678118654752f));
}

template<int KDIM, int KSPLIT, int NSTRIDE, int EPI>
__global__ __launch_bounds__(256, 2)
void gemm_ffma2(const float* __restrict__ Ain,
                const float* __restrict__ Bw,
                const float* __restrict__ bias,
                const float* __restrict__ theta) {
    __shared__ __align__(16) float As[2][BK][BM];   // 16 KB
    __shared__ __align__(16) float Bs[2][BK][BN];   // 16 KB
    const int bm = blockIdx.x;
    const int bn = (KSPLIT > 1) ? 0 : blockIdx.y;
    const int kz = (KSPLIT > 1) ? blockIdx.y : 0;
    const int tid = threadIdx.x;
    const int wid  = tid >> 5;
    const int lane = tid & 31;
    const int wm = wid >> 1, wn = wid & 1;    // warp grid 4x2
    const int lm = lane >> 3, ln = lane & 7;  // lane grid 4x8
    const int aoff = wm * 32 + lm * 8;        // A row base in tile
    const int boff = wn * 64 + ln * 8;        // B col base in tile
    const int KSEG = KDIM / KSPLIT;

    const float* A = (EPI == 0) ? Ain : (const float*)g_hid;
    const float* Ablk = A + (size_t)bm * BM * KDIM + (size_t)kz * KSEG;
    const float* Bblk = Bw + (size_t)kz * KSEG * NSTRIDE + bn * BN;

    // acc[m][np]: m = M-row (aoff+m), np = packed N pair (cols boff+2np, +2np+1)
    ull acc[8][4];
    #pragma unroll
    for (int m = 0; m < 8; m++)
        #pragma unroll
        for (int n = 0; n < 4; n++) acc[m][n] = 0ULL;

    float4 ra[2], rb[2];

    // A: 128 rows x 16 k = 512 float4 -> 2 per thread
    // B: 16 rows x 128 cols = 512 float4 -> 2 per thread
    #define LOADG(k0)                                                          \
        {                                                                      \
            _Pragma("unroll")                                                  \
            for (int it = 0; it < 2; it++) {                                   \
                int slot = it * 256 + tid;                                     \
                ra[it] = *(const float4*)(Ablk + (size_t)(slot >> 2) * KDIM +  \
                                          (k0) + (slot & 3) * 4);              \
                rb[it] = *(const float4*)(Bblk +                               \
                          (size_t)((k0) + (slot >> 5)) * NSTRIDE +             \
                          (slot & 31) * 4);                                    \
            }                                                                  \
        }
    #define STOS(buf)                                                          \
        {                                                                      \
            _Pragma("unroll")                                                  \
            for (int it = 0; it < 2; it++) {                                   \
                int slot = it * 256 + tid;                                     \
                int row = slot >> 2, k4 = (slot & 3) * 4;                      \
                As[buf][k4 + 0][row] = ra[it].x;                               \
                As[buf][k4 + 1][row] = ra[it].y;                               \
                As[buf][k4 + 2][row] = ra[it].z;                               \
                As[buf][k4 + 3][row] = ra[it].w;                               \
                *(float4*)&Bs[buf][slot >> 5][(slot & 31) * 4] = rb[it];       \
            }                                                                  \
        }

    LOADG(0);
    STOS(0);
    __syncthreads();

    const int NT = KSEG / BK;
    int cur = 0;
    for (int t = 0; t < NT; t++) {
        if (t + 1 < NT) LOADG((t + 1) * BK);
        #pragma unroll
        for (int k = 0; k < BK; k++) {
            float4 af0 = *(const float4*)&As[cur][k][aoff];
            float4 af1 = *(const float4*)&As[cur][k][aoff + 4];
            ulonglong2 b03 = *(const ulonglong2*)&Bs[cur][k][boff];
            ulonglong2 b47 = *(const ulonglong2*)&Bs[cur][k][boff + 4];
            ull ap[8] = {pack2(af0.x), pack2(af0.y), pack2(af0.z), pack2(af0.w),
                         pack2(af1.x), pack2(af1.y), pack2(af1.z), pack2(af1.w)};
            ull bp[4] = {b03.x, b03.y, b47.x, b47.y};
            #pragma unroll
            for (int m = 0; m < 8; m++)
                #pragma unroll
                for (int n = 0; n < 4; n++)
                    ffma2(acc[m][n], ap[m], bp[n]);
        }
        if (t + 1 < NT) STOS(cur ^ 1);
        __syncthreads();
        cur ^= 1;
    }

    // --- epilogue ---
    // Thread owns rows bm*128 + aoff + m (m=0..7), cols bn*128 + boff + 0..7.
    const float PI_F     = 3.14159265358979323846f;
    const float INV_2PI  = 0.15915494309189533577f;
    const float TWO_PI   = 6.28318530717958647693f;
    float* Cp = kz ? (float*)g_part : (float*)g_hid;
    #pragma unroll
    for (int m = 0; m < 8; m++) {
        int row = bm * BM + aoff + m;
        float v[8];
        #pragma unroll
        for (int n = 0; n < 4; n++) unpack2(acc[m][n], v[2 * n], v[2 * n + 1]);
        #pragma unroll
        for (int half = 0; half < 2; half++) {
            int coll = boff + half * 4;
            if (EPI == 0) {
                float4 o = {v[half*4+0], v[half*4+1], v[half*4+2], v[half*4+3]};
                *(float4*)&Cp[(size_t)row * DHH + coll] = o;
            } else {
                int col = bn * BN + coll;
                float4 th = *(const float4*)&theta[(size_t)row * CHN + col];
                const float* pth = (const float*)&th;
                float4 o;
                float* po = (float*)&o;
                #pragma unroll
                for (int j = 0; j < 4; j++) {
                    float zr = v[half * 4 + j] + bias[col + j];
                    float z = PI_F * tanhf(zr);
                    float dif = z - pth[j];
                    po[j] = dif - TWO_PI * rintf(dif * INV_2PI);
                }
                *(float4*)&g_nu[(size_t)row * CHN + col] = o;
            }
        }
    }
    #undef LOADG
    #undef STOS
}

// ---------------------------------------------------------------------------
// combine split-K partials: g_hid = gelu(g_hid + g_part + b1)
__global__ __launch_bounds__(256)
void combine_gelu(const float* __restrict__ bias) {
    const size_t n4 = (size_t)MM * DHH / 4;
    size_t i = (size_t)blockIdx.x * blockDim.x + threadIdx.x;
    const size_t stride = (size_t)gridDim.x * blockDim.x;
    for (; i < n4; i += stride) {
        float4 h = ((const float4*)g_hid)[i];
        float4 p = ((const float4*)g_part)[i];
        int colb = ((int)(i & 31)) * 4;      // DHH=128 -> 32 float4 per row
        float4 o;
        o.x = gelu_exact(h.x + p.x + bias[colb + 0]);
        o.y = gelu_exact(h.y + p.y + bias[colb + 1]);
        o.z = gelu_exact(h.z + p.z + bias[colb + 2]);
        o.w = gelu_exact(h.w + p.w + bias[colb + 3]);
        ((float4*)g_hid)[i] = o;
    }
}

// ---------------------------------------------------------------------------
// Scan pass 1: per-(b,chunk,ch4) B_c = sum_{i<L} alpha^(L-1-i) K nu_i.
// Each block handles 2 chunks (2 independent chains -> 2x MLP).
__global__ void scan_pass1() {
    int t = threadIdx.x;        // 128 threads, 4 channels each
    int c0 = blockIdx.x * 2;
    int b  = blockIdx.y;
    const float4 a4 = ((const float4*)g_alpha)[t];
    const float4 K4 = ((const float4*)g_K)[t];
    const float4* nu0 = (const float4*)g_nu +
                        ((size_t)b * TT + (size_t)c0 * SCAN_L) * (CHN / 4) + t;
    const float4* nu1 = nu0 + (size_t)SCAN_L * (CHN / 4);
    float4 s0 = {0.f,0.f,0.f,0.f}, s1 = {0.f,0.f,0.f,0.f};
    #pragma unroll
    for (int i = 0; i < SCAN_L; i++) {
        float4 v0 = nu0[(size_t)i * (CHN / 4)];
        float4 v1 = nu1[(size_t)i * (CHN / 4)];
        s0.x = fmaf(a4.x, s0.x, K4.x * v0.x);
        s0.y = fmaf(a4.y, s0.y, K4.y * v0.y);
        s0.z = fmaf(a4.z, s0.z, K4.z * v0.z);
        s0.w = fmaf(a4.w, s0.w, K4.w * v0.w);
        s1.x = fmaf(a4.x, s1.x, K4.x * v1.x);
        s1.y = fmaf(a4.y, s1.y, K4.y * v1.y);
        s1.z = fmaf(a4.z, s1.z, K4.z * v1.z);
        s1.w = fmaf(a4.w, s1.w, K4.w * v1.w);
    }
    ((float4*)g_Bmat)[((size_t)b * SCAN_C + c0) * (CHN / 4) + t] = s0;
    ((float4*)g_Bmat)[((size_t)b * SCAN_C + c0 + 1) * (CHN / 4) + t] = s1;
}

// Scan pass 2a: within-group carries (grid NGRP x BB).
__global__ void scan_pass2a() {
    int t = threadIdx.x;        // 128
    int g = blockIdx.x;         // 16
    int b = blockIdx.y;
    const float4 aL = ((const float4*)g_alphaL)[t];
    float4 carry = {0.f, 0.f, 0.f, 0.f};
    #pragma unroll 4
    for (int j = 0; j < GRP; j++) {
        size_t idx = ((size_t)b * SCAN_C + g * GRP + j) * (CHN / 4) + t;
        ((float4*)g_D0)[idx] = carry;
        float4 Bv = ((const float4*)g_Bmat)[idx];
        carry.x = fmaf(aL.x, carry.x, Bv.x);
        carry.y = fmaf(aL.y, carry.y, Bv.y);
        carry.z = fmaf(aL.z, carry.z, Bv.z);
        carry.w = fmaf(aL.w, carry.w, Bv.w);
    }
    ((float4*)g_G)[((size_t)b * NGRP + g) * (CHN / 4) + t] = carry;
}

// Scan pass 2b: scan group aggregates (16 serial steps).
__global__ void scan_pass2b() {
    int t = threadIdx.x;        // 128
    int b = blockIdx.x;         // 2
    const float4 aL32 = ((const float4*)g_alphaL32)[t];
    float4 carry = {0.f, 0.f, 0.f, 0.f};
    #pragma unroll
    for (int g = 0; g < NGRP; g++) {
        size_t idx = ((size_t)b * NGRP + g) * (CHN / 4) + t;
        ((float4*)g_C)[idx] = carry;
        float4 Gv = ((const float4*)g_G)[idx];
        carry.x = fmaf(aL32.x, carry.x, Gv.x);
        carry.y = fmaf(aL32.y, carry.y, Gv.y);
        carry.z = fmaf(aL32.z, carry.z, Gv.z);
        carry.w = fmaf(aL32.w, carry.w, Gv.w);
    }
}

// Scan pass 3: replay 2 chunks per block with full carry, write d and theta_hat.
__global__ void scan_pass3(const float* __restrict__ theta,
                           float* __restrict__ out) {
    int t = threadIdx.x;
    int c0 = blockIdx.x * 2;
    int b  = blockIdx.y;
    const float4 a4 = ((const float4*)g_alpha)[t];
    const float4 K4 = ((const float4*)g_K)[t];

    float4 d[2];
    #pragma unroll
    for (int cc = 0; cc < 2; cc++) {
        int c = c0 + cc;
        int g = c >> 5, jl = c & 31;
        float4 d0 = ((const float4*)g_D0)[((size_t)b * SCAN_C + c) * (CHN / 4) + t];
        float4 Cg = ((const float4*)g_C)[((size_t)b * NGRP + g) * (CHN / 4) + t];
        float4 ap = ((const float4*)g_aLp)[(size_t)jl * (CHN / 4) + t];
        d[cc].x = fmaf(Cg.x, ap.x, d0.x);
        d[cc].y = fmaf(Cg.y, ap.y, d0.y);
        d[cc].z = fmaf(Cg.z, ap.z, d0.z);
        d[cc].w = fmaf(Cg.w, ap.w, d0.w);
    }

    size_t base = ((size_t)b * TT + (size_t)c0 * SCAN_L) * (CHN / 4) + t;
    const float4* nu4 = (const float4*)g_nu + base;
    const float4* th4 = (const float4*)theta + base;
    float4* outh = (float4*)out + base;
    float4* outd = (float4*)(out + OFF_D) + base;
    const size_t cstep = (size_t)SCAN_L * (CHN / 4);
    #pragma unroll
    for (int i = 0; i < SCAN_L; i++) {
        size_t i0 = (size_t)i * (CHN / 4);
        size_t i1 = i0 + cstep;
        float4 v0 = nu4[i0], v1 = nu4[i1];
        float4 t0 = th4[i0], t1 = th4[i1];
        d[0].x = fmaf(a4.x, d[0].x, K4.x * v0.x);
        d[0].y = fmaf(a4.y, d[0].y, K4.y * v0.y);
        d[0].z = fmaf(a4.z, d[0].z, K4.z * v0.z);
        d[0].w = fmaf(a4.w, d[0].w, K4.w * v0.w);
        d[1].x = fmaf(a4.x, d[1].x, K4.x * v1.x);
        d[1].y = fmaf(a4.y, d[1].y, K4.y * v1.y);
        d[1].z = fmaf(a4.z, d[1].z, K4.z * v1.z);
        d[1].w = fmaf(a4.w, d[1].w, K4.w * v1.w);
        outd[i0] = d[0];
        outd[i1] = d[1];
        float4 o0 = {t0.x + d[0].x, t0.y + d[0].y, t0.z + d[0].z, t0.w + d[0].w};
        float4 o1 = {t1.x + d[1].x, t1.y + d[1].y, t1.z + d[1].z, t1.w + d[1].w};
        outh[i0] = o0;
        outh[i1] = o1;
    }
}

// ---------------------------------------------------------------------------
extern "C" void kernel_launch(void* const* d_in, const int* in_sizes, int n_in,
                              void* d_out, int out_size) {
    const float* theta   = (const float*)d_in[0];  // (B,T,H,NB)
    const float* content = (const float*)d_in[1];  // (B,T,D)
    const float* W1      = (const float*)d_in[2];  // (D,DH)
    const float* b1      = (const float*)d_in[3];  // (DH,)
    const float* W2      = (const float*)d_in[4];  // (DH,H*NB)
    const float* b2      = (const float*)d_in[5];  // (H*NB,)
    const float* lQ      = (const float*)d_in[6];  // (H,NB)
    const float* lR      = (const float*)d_in[7];  // (H,NB)
    float* out = (float*)d_out;

    kstar_kernel<<<1, CHN>>>(lQ, lR, out);
    // GEMM1 split-K=2: raw partials into g_hid / g_part
    gemm_ffma2<DD, 2, DHH, 0><<<dim3(MM / BM, 2), 256>>>(content, W1, b1, nullptr);
    combine_gelu<<<2048, 256>>>(b1);
    // GEMM2
    gemm_ffma2<DHH, 1, CHN, 1><<<dim3(MM / BM, CHN / BN), 256>>>(nullptr, W2, b2, theta);
    scan_pass1<<<dim3(SCAN_C / 2, BB), 128>>>();
    scan_pass2a<<<dim3(NGRP, BB), 128>>>();
    scan_pass2b<<<BB, 128>>>();
    scan_pass3<<<dim3(SCAN_C / 2, BB), 128>>>(theta, out);
}

// round 14
// speedup vs baseline: 1.5163x; 1.0508x over previous
#include <cuda_runtime.h>
#include <math.h>

// Problem constants
#define BB   2
#define TT   8192
#define HH   16
#define NBB  32
#define DD   1024
#define DHH  128
#define CHN  (HH*NBB)          // 512
#define MM   (BB*TT)           // 16384

// Scan chunking
#define SCAN_L 16
#define SCAN_C (TT/SCAN_L)     // 512 chunks
#define GRP    32              // chunks per group
#define NGRP   (SCAN_C/GRP)    // 16 groups

// Output layout: theta_hat [B,T,H,NB], d [B,T,H,NB], K_star [H,NB]
#define OFF_D  ((size_t)BB*TT*CHN)     // 8388608
#define OFF_K  (2*OFF_D)               // 16777216

// Scratch (static device allocations; no cudaMalloc allowed)
__device__ __align__(16) float g_hid [(size_t)MM*DHH];      // 8.4 MB
__device__ __align__(16) float g_part[(size_t)MM*DHH];      // 8.4 MB (split-K partial)
__device__ __align__(16) float g_nu  [(size_t)MM*CHN];      // 33.5 MB
__device__ __align__(16) float g_K[CHN];
__device__ __align__(16) float g_alpha[CHN];
__device__ __align__(16) float g_alphaL[CHN];               // alpha^SCAN_L
__device__ __align__(16) float g_alphaL32[CHN];             // alpha^(SCAN_L*GRP)
__device__ __align__(16) float g_aLp[GRP][CHN];             // alphaL^j
__device__ __align__(16) float g_Bmat[(size_t)BB*SCAN_C*CHN];  // 2 MB
__device__ __align__(16) float g_D0 [(size_t)BB*SCAN_C*CHN];   // 2 MB
__device__ __align__(16) float g_G[(size_t)BB*NGRP*CHN];
__device__ __align__(16) float g_C[(size_t)BB*NGRP*CHN];

typedef unsigned long long ull;

// ---------------------------------------------------------------------------
// packed fp32x2 helpers (sm_103a FFMA2)
__device__ __forceinline__ void ffma2(ull& d, ull a, ull b) {
    asm("fma.rn.f32x2 %0, %1, %2, %0;" : "+l"(d) : "l"(a), "l"(b));
}
__device__ __forceinline__ ull pack2(float x) {
    ull r; asm("mov.b64 %0, {%1, %1};" : "=l"(r) : "f"(x)); return r;
}
__device__ __forceinline__ void unpack2(ull v, float& lo, float& hi) {
    asm("mov.b64 {%0, %1}, %2;" : "=f"(lo), "=f"(hi) : "l"(v));
}

// ---------------------------------------------------------------------------
// K* = (P+Q)/(P+Q+R),  P = (-Q + sqrt(Q^2+4QR))/2  + scan constants
__global__ void kstar_kernel(const float* __restrict__ lQ,
                             const float* __restrict__ lR,
                             float* __restrict__ out) {
    int c = threadIdx.x;  // 512
    float Q = expf(lQ[c]);
    float R = expf(lR[c]);
    float P_post = 0.5f * (-Q + sqrtf(Q * Q + 4.0f * Q * R));
    float P_pred = P_post + Q;
    float Kc = P_pred / (P_pred + R);
    float a = 1.0f - Kc;
    g_K[c] = Kc;
    g_alpha[c] = a;
    float aL = powf(a, (float)SCAN_L);
    g_alphaL[c] = aL;
    float p = 1.0f;
    #pragma unroll
    for (int j = 0; j < GRP; j++) { g_aLp[j][c] = p; p *= aL; }
    g_alphaL32[c] = p;                 // aL^GRP
    out[OFF_K + c] = Kc;
}

// ---------------------------------------------------------------------------
// FFMA2 tiled fp32 GEMM, double-buffered smem, 2D warp tiling.
// CTA tile 128x128, BK=16, 256 threads, 2 CTAs/SM.
// Warp grid 4(M) x 2(N); lanes 4(lm) x 8(ln); thread tile 8M x 8N.
// A smem: k-major, XOR-swizzled (row ^ (k4<<1)) -> conflict-free STS.32 & LDS.128.
// B smem: filled by cp.async.cg (gmem layout matches), fragment double-buffered.
// EPI==0: raw partial -> (kz ? g_part : g_hid)  [GEMM1 split-K, grid (128, 2)]
// EPI==1: wrap(pi*tanh(. + b2) - theta) -> g_nu [GEMM2, grid (128, 4)]
#define BM 128
#define BN 128
#define BK 16

__device__ __forceinline__ float gelu_exact(float x) {
    return 0.5f * x * (1.0f + erff(x * 0.70710678118654752f));
}

template<int KDIM, int KSPLIT, int NSTRIDE, int EPI>
__global__ __launch_bounds__(256, 2)
void gemm_ffma2(const float* __restrict__ Ain,
                const float* __restrict__ Bw,
                const float* __restrict__ bias,
                const float* __restrict__ theta) {
    __shared__ __align__(16) float As[2][BK][BM];   // 16 KB (swizzled)
    __shared__ __align__(16) float Bs[2][BK][BN];   // 16 KB
    const int bm = blockIdx.x;
    const int bn = (KSPLIT > 1) ? 0 : blockIdx.y;
    const int kz = (KSPLIT > 1) ? blockIdx.y : 0;
    const int tid = threadIdx.x;
    const int wid  = tid >> 5;
    const int lane = tid & 31;
    const int wm = wid >> 1, wn = wid & 1;    // warp grid 4x2
    const int lm = lane >> 3, ln = lane & 7;  // lane grid 4x8
    const int aoff = wm * 32 + lm * 8;        // A row base in tile
    const int boff = wn * 64 + ln * 8;        // B col base in tile
    const int KSEG = KDIM / KSPLIT;

    const float* A = (EPI == 0) ? Ain : (const float*)g_hid;
    const float* Ablk = A + (size_t)bm * BM * KDIM + (size_t)kz * KSEG;
    const float* Bblk = Bw + (size_t)kz * KSEG * NSTRIDE + bn * BN;

    const unsigned bs_base = (unsigned)__cvta_generic_to_shared(&Bs[0][0][0]);

    // acc[m][np]: m = M-row (aoff+m), np = packed N pair (cols boff+2np, +2np+1)
    ull acc[8][4];
    #pragma unroll
    for (int m = 0; m < 8; m++)
        #pragma unroll
        for (int n = 0; n < 4; n++) acc[m][n] = 0ULL;

    float4 ra[2];

    // A: 128 rows x 16 k = 512 float4 -> 2 LDG per thread
    #define LOADGA(k0)                                                         \
        {                                                                      \
            _Pragma("unroll")                                                  \
            for (int it = 0; it < 2; it++) {                                   \
                int slot = it * 256 + tid;                                     \
                ra[it] = *(const float4*)(Ablk + (size_t)(slot >> 2) * KDIM +  \
                                          (k0) + (slot & 3) * 4);              \
            }                                                                  \
        }
    // A staged regs -> smem, swizzled: row' = row ^ (kq*8), kq = slot&3
    #define STOSA(buf)                                                         \
        {                                                                      \
            _Pragma("unroll")                                                  \
            for (int it = 0; it < 2; it++) {                                   \
                int slot = it * 256 + tid;                                     \
                int row = slot >> 2, kq = slot & 3;                            \
                int rowp = row ^ (kq << 3);                                    \
                int k4 = kq * 4;                                               \
                As[buf][k4 + 0][rowp] = ra[it].x;                              \
                As[buf][k4 + 1][rowp] = ra[it].y;                              \
                As[buf][k4 + 2][rowp] = ra[it].z;                              \
                As[buf][k4 + 3][rowp] = ra[it].w;                              \
            }                                                                  \
        }
    // B: 16 rows x 128 cols, cp.async 16B copies (layout identical to gmem)
    #define CPB(buf, k0)                                                       \
        {                                                                      \
            _Pragma("unroll")                                                  \
            for (int it = 0; it < 2; it++) {                                   \
                int slot = it * 256 + tid;                                     \
                int brow = slot >> 5, bcol = (slot & 31) * 4;                  \
                unsigned da = bs_base +                                        \
                    (unsigned)(((buf) * BK + brow) * BN + bcol) * 4u;          \
                const float* src = Bblk + (size_t)((k0) + brow) * NSTRIDE      \
                                   + bcol;                                     \
                asm volatile("cp.async.cg.shared.global [%0], [%1], 16;"      \
                             :: "r"(da), "l"(src) : "memory");                 \
            }                                                                  \
            asm volatile("cp.async.commit_group;" ::: "memory");               \
        }
    #define CPWAIT() asm volatile("cp.async.wait_group 0;" ::: "memory")

    // B fragment (double-buffered), A fragment (single)
    ull bp[2][4];
    #define LDFRAGB(f, k)                                                      \
        {                                                                      \
            ulonglong2 b03 = *(const ulonglong2*)&Bs[cur][k][boff];            \
            ulonglong2 b47 = *(const ulonglong2*)&Bs[cur][k][boff + 4];        \
            bp[f][0] = b03.x; bp[f][1] = b03.y;                                \
            bp[f][2] = b47.x; bp[f][3] = b47.y;                                \
        }

    LOADGA(0);
    CPB(0, 0);
    STOSA(0);
    CPWAIT();
    __syncthreads();

    const int NT = KSEG / BK;
    int cur = 0;
    for (int t = 0; t < NT; t++) {
        if (t + 1 < NT) {
            LOADGA((t + 1) * BK);
            CPB(cur ^ 1, (t + 1) * BK);
        }
        LDFRAGB(0, 0);
        #pragma unroll
        for (int k = 0; k < BK; k++) {
            if (k + 1 < BK) LDFRAGB((k + 1) & 1, k + 1);
            int ab = aoff ^ (((k) >> 2) << 3);
            float4 af0 = *(const float4*)&As[cur][k][ab];
            float4 af1 = *(const float4*)&As[cur][k][ab + 4];
            ull ap[8] = {pack2(af0.x), pack2(af0.y), pack2(af0.z), pack2(af0.w),
                         pack2(af1.x), pack2(af1.y), pack2(af1.z), pack2(af1.w)};
            const ull* bpk = bp[k & 1];
            #pragma unroll
            for (int m = 0; m < 8; m++)
                #pragma unroll
                for (int n = 0; n < 4; n++)
                    ffma2(acc[m][n], ap[m], bpk[n]);
        }
        if (t + 1 < NT) STOSA(cur ^ 1);
        CPWAIT();
        __syncthreads();
        cur ^= 1;
    }

    // --- epilogue ---
    // Thread owns rows bm*128 + aoff + m (m=0..7), cols bn*128 + boff + 0..7.
    const float PI_F     = 3.14159265358979323846f;
    const float INV_2PI  = 0.15915494309189533577f;
    const float TWO_PI   = 6.28318530717958647693f;
    float* Cp = kz ? (float*)g_part : (float*)g_hid;
    #pragma unroll
    for (int m = 0; m < 8; m++) {
        int row = bm * BM + aoff + m;
        float v[8];
        #pragma unroll
        for (int n = 0; n < 4; n++) unpack2(acc[m][n], v[2 * n], v[2 * n + 1]);
        #pragma unroll
        for (int half = 0; half < 2; half++) {
            int coll = boff + half * 4;
            if (EPI == 0) {
                float4 o = {v[half*4+0], v[half*4+1], v[half*4+2], v[half*4+3]};
                *(float4*)&Cp[(size_t)row * DHH + coll] = o;
            } else {
                int col = bn * BN + coll;
                float4 th = *(const float4*)&theta[(size_t)row * CHN + col];
                const float* pth = (const float*)&th;
                float4 o;
                float* po = (float*)&o;
                #pragma unroll
                for (int j = 0; j < 4; j++) {
                    float zr = v[half * 4 + j] + bias[col + j];
                    float z = PI_F * tanhf(zr);
                    float dif = z - pth[j];
                    po[j] = dif - TWO_PI * rintf(dif * INV_2PI);
                }
                *(float4*)&g_nu[(size_t)row * CHN + col] = o;
            }
        }
    }
    #undef LOADGA
    #undef STOSA
    #undef CPB
    #undef CPWAIT
    #undef LDFRAGB
}

// ---------------------------------------------------------------------------
// combine split-K partials: g_hid = gelu(g_hid + g_part + b1)
__global__ __launch_bounds__(256)
void combine_gelu(const float* __restrict__ bias) {
    const size_t n4 = (size_t)MM * DHH / 4;
    size_t i = (size_t)blockIdx.x * blockDim.x + threadIdx.x;
    const size_t stride = (size_t)gridDim.x * blockDim.x;
    for (; i < n4; i += stride) {
        float4 h = ((const float4*)g_hid)[i];
        float4 p = ((const float4*)g_part)[i];
        int colb = ((int)(i & 31)) * 4;      // DHH=128 -> 32 float4 per row
        float4 o;
        o.x = gelu_exact(h.x + p.x + bias[colb + 0]);
        o.y = gelu_exact(h.y + p.y + bias[colb + 1]);
        o.z = gelu_exact(h.z + p.z + bias[colb + 2]);
        o.w = gelu_exact(h.w + p.w + bias[colb + 3]);
        ((float4*)g_hid)[i] = o;
    }
}

// ---------------------------------------------------------------------------
// Scan pass 1: per-(b,chunk,ch4) B_c = sum_{i<L} alpha^(L-1-i) K nu_i.
// Each block handles 2 chunks (2 independent chains -> 2x MLP).
__global__ void scan_pass1() {
    int t = threadIdx.x;        // 128 threads, 4 channels each
    int c0 = blockIdx.x * 2;
    int b  = blockIdx.y;
    const float4 a4 = ((const float4*)g_alpha)[t];
    const float4 K4 = ((const float4*)g_K)[t];
    const float4* nu0 = (const float4*)g_nu +
                        ((size_t)b * TT + (size_t)c0 * SCAN_L) * (CHN / 4) + t;
    const float4* nu1 = nu0 + (size_t)SCAN_L * (CHN / 4);
    float4 s0 = {0.f,0.f,0.f,0.f}, s1 = {0.f,0.f,0.f,0.f};
    #pragma unroll
    for (int i = 0; i < SCAN_L; i++) {
        float4 v0 = nu0[(size_t)i * (CHN / 4)];
        float4 v1 = nu1[(size_t)i * (CHN / 4)];
        s0.x = fmaf(a4.x, s0.x, K4.x * v0.x);
        s0.y = fmaf(a4.y, s0.y, K4.y * v0.y);
        s0.z = fmaf(a4.z, s0.z, K4.z * v0.z);
        s0.w = fmaf(a4.w, s0.w, K4.w * v0.w);
        s1.x = fmaf(a4.x, s1.x, K4.x * v1.x);
        s1.y = fmaf(a4.y, s1.y, K4.y * v1.y);
        s1.z = fmaf(a4.z, s1.z, K4.z * v1.z);
        s1.w = fmaf(a4.w, s1.w, K4.w * v1.w);
    }
    ((float4*)g_Bmat)[((size_t)b * SCAN_C + c0) * (CHN / 4) + t] = s0;
    ((float4*)g_Bmat)[((size_t)b * SCAN_C + c0 + 1) * (CHN / 4) + t] = s1;
}

// Scan pass 2a: within-group carries (grid NGRP x BB).
__global__ void scan_pass2a() {
    int t = threadIdx.x;        // 128
    int g = blockIdx.x;         // 16
    int b = blockIdx.y;
    const float4 aL = ((const float4*)g_alphaL)[t];
    float4 carry = {0.f, 0.f, 0.f, 0.f};
    #pragma unroll 4
    for (int j = 0; j < GRP; j++) {
        size_t idx = ((size_t)b * SCAN_C + g * GRP + j) * (CHN / 4) + t;
        ((float4*)g_D0)[idx] = carry;
        float4 Bv = ((const float4*)g_Bmat)[idx];
        carry.x = fmaf(aL.x, carry.x, Bv.x);
        carry.y = fmaf(aL.y, carry.y, Bv.y);
        carry.z = fmaf(aL.z, carry.z, Bv.z);
        carry.w = fmaf(aL.w, carry.w, Bv.w);
    }
    ((float4*)g_G)[((size_t)b * NGRP + g) * (CHN / 4) + t] = carry;
}

// Scan pass 2b: scan group aggregates (16 serial steps).
__global__ void scan_pass2b() {
    int t = threadIdx.x;        // 128
    int b = blockIdx.x;         // 2
    const float4 aL32 = ((const float4*)g_alphaL32)[t];
    float4 carry = {0.f, 0.f, 0.f, 0.f};
    #pragma unroll
    for (int g = 0; g < NGRP; g++) {
        size_t idx = ((size_t)b * NGRP + g) * (CHN / 4) + t;
        ((float4*)g_C)[idx] = carry;
        float4 Gv = ((const float4*)g_G)[idx];
        carry.x = fmaf(aL32.x, carry.x, Gv.x);
        carry.y = fmaf(aL32.y, carry.y, Gv.y);
        carry.z = fmaf(aL32.z, carry.z, Gv.z);
        carry.w = fmaf(aL32.w, carry.w, Gv.w);
    }
}

// Scan pass 3: replay 2 chunks per block with full carry, write d and theta_hat.
__global__ void scan_pass3(const float* __restrict__ theta,
                           float* __restrict__ out) {
    int t = threadIdx.x;
    int c0 = blockIdx.x * 2;
    int b  = blockIdx.y;
    const float4 a4 = ((const float4*)g_alpha)[t];
    const float4 K4 = ((const float4*)g_K)[t];

    float4 d[2];
    #pragma unroll
    for (int cc = 0; cc < 2; cc++) {
        int c = c0 + cc;
        int g = c >> 5, jl = c & 31;
        float4 d0 = ((const float4*)g_D0)[((size_t)b * SCAN_C + c) * (CHN / 4) + t];
        float4 Cg = ((const float4*)g_C)[((size_t)b * NGRP + g) * (CHN / 4) + t];
        float4 ap = ((const float4*)g_aLp)[(size_t)jl * (CHN / 4) + t];
        d[cc].x = fmaf(Cg.x, ap.x, d0.x);
        d[cc].y = fmaf(Cg.y, ap.y, d0.y);
        d[cc].z = fmaf(Cg.z, ap.z, d0.z);
        d[cc].w = fmaf(Cg.w, ap.w, d0.w);
    }

    size_t base = ((size_t)b * TT + (size_t)c0 * SCAN_L) * (CHN / 4) + t;
    const float4* nu4 = (const float4*)g_nu + base;
    const float4* th4 = (const float4*)theta + base;
    float4* outh = (float4*)out + base;
    float4* outd = (float4*)(out + OFF_D) + base;
    const size_t cstep = (size_t)SCAN_L * (CHN / 4);
    #pragma unroll
    for (int i = 0; i < SCAN_L; i++) {
        size_t i0 = (size_t)i * (CHN / 4);
        size_t i1 = i0 + cstep;
        float4 v0 = nu4[i0], v1 = nu4[i1];
        float4 t0 = th4[i0], t1 = th4[i1];
        d[0].x = fmaf(a4.x, d[0].x, K4.x * v0.x);
        d[0].y = fmaf(a4.y, d[0].y, K4.y * v0.y);
        d[0].z = fmaf(a4.z, d[0].z, K4.z * v0.z);
        d[0].w = fmaf(a4.w, d[0].w, K4.w * v0.w);
        d[1].x = fmaf(a4.x, d[1].x, K4.x * v1.x);
        d[1].y = fmaf(a4.y, d[1].y, K4.y * v1.y);
        d[1].z = fmaf(a4.z, d[1].z, K4.z * v1.z);
        d[1].w = fmaf(a4.w, d[1].w, K4.w * v1.w);
        outd[i0] = d[0];
        outd[i1] = d[1];
        float4 o0 = {t0.x + d[0].x, t0.y + d[0].y, t0.z + d[0].z, t0.w + d[0].w};
        float4 o1 = {t1.x + d[1].x, t1.y + d[1].y, t1.z + d[1].z, t1.w + d[1].w};
        outh[i0] = o0;
        outh[i1] = o1;
    }
}

// ---------------------------------------------------------------------------
extern "C" void kernel_launch(void* const* d_in, const int* in_sizes, int n_in,
                              void* d_out, int out_size) {
    const float* theta   = (const float*)d_in[0];  // (B,T,H,NB)
    const float* content = (const float*)d_in[1];  // (B,T,D)
    const float* W1      = (const float*)d_in[2];  // (D,DH)
    const float* b1      = (const float*)d_in[3];  // (DH,)
    const float* W2      = (const float*)d_in[4];  // (DH,H*NB)
    const float* b2      = (const float*)d_in[5];  // (H*NB,)
    const float* lQ      = (const float*)d_in[6];  // (H,NB)
    const float* lR      = (const float*)d_in[7];  // (H,NB)
    float* out = (float*)d_out;

    kstar_kernel<<<1, CHN>>>(lQ, lR, out);
    // GEMM1 split-K=2: raw partials into g_hid / g_part
    gemm_ffma2<DD, 2, DHH, 0><<<dim3(MM / BM, 2), 256>>>(content, W1, b1, nullptr);
    combine_gelu<<<2048, 256>>>(b1);
    // GEMM2
    gemm_ffma2<DHH, 1, CHN, 1><<<dim3(MM / BM, CHN / BN), 256>>>(nullptr, W2, b2, theta);
    scan_pass1<<<dim3(SCAN_C / 2, BB), 128>>>();
    scan_pass2a<<<dim3(NGRP, BB), 128>>>();
    scan_pass2b<<<BB, 128>>>();
    scan_pass3<<<dim3(SCAN_C / 2, BB), 128>>>(theta, out);
}